// round 3
// baseline (speedup 1.0000x reference)
#include <cuda_runtime.h>

#define NB 8
#define NH 8
#define NN 1024
#define NC 512
#define ND 64
#define S2 1024
#define SPANP 512

// -------- scratch (device globals; no runtime allocation allowed) --------
static __device__ float g_Q[NB*NH*NN*ND];          // 16 MB  [b][h][n][d]
static __device__ float g_K[NB*NH*NN*ND];
static __device__ float g_V[NB*NH*NN*ND];
static __device__ float g_pK[NH*S2*ND];            // 2 MB   [h][p][d]
static __device__ float g_pQ[NH*S2*ND];
static __device__ float g_C[(size_t)NB*NH*NN*S2];  // 256 MB [bh][q][p] = Q·posK^T
static __device__ float g_D[(size_t)NB*NH*NN*S2];  // 256 MB [bh][k][p] = K·posQ^T

// =====================================================================
// Projection GEMM: out = A[M,512] @ W[512,512] + bias, head-split output
// 128x128 block, 256 threads, 8x8 microtile, BK=16
// mode 0: out[((b*8+h)*1024 + n)*64 + dd]  (b=m>>10, n=m&1023)
// mode 1: out[(h*1024 + p)*64 + dd]        (p=m)
// =====================================================================
__global__ __launch_bounds__(256) void proj_kernel(
    const float* __restrict__ A, const float* __restrict__ W,
    const float* __restrict__ bias, int which, int M, int mode)
{
    float* out = (which==0)?g_Q:(which==1)?g_K:(which==2)?g_V:(which==3)?g_pK:g_pQ;
    __shared__ float As[16][132];   // As[k][m]  (transposed)
    __shared__ float Bs[16][132];   // Bs[k][n]
    const int tid = threadIdx.x;
    const int tx = tid & 15, ty = tid >> 4;
    const int n0 = blockIdx.x * 128, m0 = blockIdx.y * 128;

    float acc[8][8];
    #pragma unroll
    for (int i = 0; i < 8; i++)
        #pragma unroll
        for (int j = 0; j < 8; j++) acc[i][j] = 0.f;

    const int ar = tid >> 2, aq = tid & 3;   // A load: row, col-quad
    const int bc = tid & 31, bk = tid >> 5;  // B load: col-quad, row

    // prefetch first k-slab
    float4 pa[2], pb[2];
    #pragma unroll
    for (int rr = 0; rr < 2; rr++) {
        pa[rr] = *(const float4*)(A + (size_t)(m0 + ar + rr*64)*NC + aq*4);
        pb[rr] = *(const float4*)(W + (size_t)(bk + rr*8)*NC + n0 + bc*4);
    }

    for (int k0 = 0; k0 < NC; k0 += 16) {
        #pragma unroll
        for (int rr = 0; rr < 2; rr++) {
            int row = ar + rr*64;
            As[aq*4+0][row] = pa[rr].x; As[aq*4+1][row] = pa[rr].y;
            As[aq*4+2][row] = pa[rr].z; As[aq*4+3][row] = pa[rr].w;
            *(float4*)&Bs[bk + rr*8][bc*4] = pb[rr];
        }
        __syncthreads();
        if (k0 + 16 < NC) {
            #pragma unroll
            for (int rr = 0; rr < 2; rr++) {
                pa[rr] = *(const float4*)(A + (size_t)(m0 + ar + rr*64)*NC + (k0+16) + aq*4);
                pb[rr] = *(const float4*)(W + (size_t)(k0+16 + bk + rr*8)*NC + n0 + bc*4);
            }
        }
        #pragma unroll
        for (int kk = 0; kk < 16; kk++) {
            float a[8], b[8];
            *(float4*)&a[0] = *(float4*)&As[kk][ty*4];
            *(float4*)&a[4] = *(float4*)&As[kk][64 + ty*4];
            *(float4*)&b[0] = *(float4*)&Bs[kk][tx*4];
            *(float4*)&b[4] = *(float4*)&Bs[kk][64 + tx*4];
            #pragma unroll
            for (int i = 0; i < 8; i++)
                #pragma unroll
                for (int j = 0; j < 8; j++)
                    acc[i][j] += a[i]*b[j];
        }
        __syncthreads();
    }

    #pragma unroll
    for (int i = 0; i < 8; i++) {
        int m = m0 + ((i < 4) ? (ty*4 + i) : (64 + ty*4 + i - 4));
        int bb = mode ? 0 : (m >> 10);
        int r  = mode ? m : (m & 1023);
        #pragma unroll
        for (int j = 0; j < 8; j++) {
            int c = n0 + ((j < 4) ? (tx*4 + j) : (64 + tx*4 + j - 4));
            int h = c >> 6, dd = c & 63;
            out[(((size_t)bb*NH + h)*NN + r)*ND + dd] = acc[i][j] + bias[c];
        }
    }
}

// =====================================================================
// C/D GEMM (NT, K=64): which=0: C[bh][q][p] = Q[bh][q]·posK[h][p]
//                      which=1: D[bh][k][p] = K[bh][k]·posQ[h][p]
// 128x128 block, 256 threads, 8x8 microtile
// =====================================================================
__global__ __launch_bounds__(256) void cd_kernel(int which)
{
    const int bh = blockIdx.z, h = bh & 7;
    const float* A = (which==0 ? g_Q : g_K) + (size_t)bh*NN*ND;
    const float* P = (which==0 ? g_pK : g_pQ) + (size_t)h*S2*ND;
    float* O = (which==0 ? g_C : g_D) + (size_t)bh*NN*S2;

    __shared__ float As[16][132];   // As[k][m]
    __shared__ float Bs[16][132];   // Bs[k][p]
    const int tid = threadIdx.x;
    const int tx = tid & 15, ty = tid >> 4;
    const int n0 = blockIdx.x * 128, m0 = blockIdx.y * 128;

    float acc[8][8];
    #pragma unroll
    for (int i = 0; i < 8; i++)
        #pragma unroll
        for (int j = 0; j < 8; j++) acc[i][j] = 0.f;

    const int ar = tid >> 2, aq = tid & 3;

    float4 pa[2], pb[2];
    #pragma unroll
    for (int rr = 0; rr < 2; rr++) {
        pa[rr] = *(const float4*)(A + (size_t)(m0 + ar + rr*64)*ND + aq*4);
        pb[rr] = *(const float4*)(P + (size_t)(n0 + ar + rr*64)*ND + aq*4);
    }

    #pragma unroll
    for (int k0 = 0; k0 < ND; k0 += 16) {
        #pragma unroll
        for (int rr = 0; rr < 2; rr++) {
            int row = ar + rr*64;
            As[aq*4+0][row] = pa[rr].x; As[aq*4+1][row] = pa[rr].y;
            As[aq*4+2][row] = pa[rr].z; As[aq*4+3][row] = pa[rr].w;
            Bs[aq*4+0][row] = pb[rr].x; Bs[aq*4+1][row] = pb[rr].y;
            Bs[aq*4+2][row] = pb[rr].z; Bs[aq*4+3][row] = pb[rr].w;
        }
        __syncthreads();
        if (k0 + 16 < ND) {
            #pragma unroll
            for (int rr = 0; rr < 2; rr++) {
                pa[rr] = *(const float4*)(A + (size_t)(m0 + ar + rr*64)*ND + (k0+16) + aq*4);
                pb[rr] = *(const float4*)(P + (size_t)(n0 + ar + rr*64)*ND + (k0+16) + aq*4);
            }
        }
        #pragma unroll
        for (int kk = 0; kk < 16; kk++) {
            float a[8], b[8];
            *(float4*)&a[0] = *(float4*)&As[kk][ty*4];
            *(float4*)&a[4] = *(float4*)&As[kk][64 + ty*4];
            *(float4*)&b[0] = *(float4*)&Bs[kk][tx*4];
            *(float4*)&b[4] = *(float4*)&Bs[kk][64 + tx*4];
            #pragma unroll
            for (int i = 0; i < 8; i++)
                #pragma unroll
                for (int j = 0; j < 8; j++)
                    acc[i][j] += a[i]*b[j];
        }
        __syncthreads();
    }

    #pragma unroll
    for (int i = 0; i < 8; i++) {
        int m = m0 + ((i < 4) ? (ty*4 + i) : (64 + ty*4 + i - 4));
        float4 v0 = make_float4(acc[i][0], acc[i][1], acc[i][2], acc[i][3]);
        float4 v1 = make_float4(acc[i][4], acc[i][5], acc[i][6], acc[i][7]);
        *(float4*)(O + (size_t)m*S2 + n0 + tx*4)      = v0;
        *(float4*)(O + (size_t)m*S2 + n0 + 64 + tx*4) = v1;
    }
}

// =====================================================================
// Fused flash attention with relative-position gather.
// Grid: (16 q-tiles, 64 bh). 256 threads. 64x64 tiles, 4x4 microtile.
// scores[q,k] = (Q·K + C[q,p] + D[k,p]) / sqrt(192),  p = clip(q-k+512)
// K/V global loads are software-pipelined one k-tile ahead.
// =====================================================================
__global__ __launch_bounds__(256) void attn_kernel(float* __restrict__ out)
{
    extern __shared__ float sm[];
    float* Qt = sm;              // [64][68]: Qt[dd][q]
    float* Kt = Qt + 64*68;      // [64][68]: Kt[dd][k]
    float* Vs = Kt + 64*68;      // [64][68]: Vs[k][dd]
    float* Pt = Vs + 64*68;      // [64][68]: Pt[k][q]
    float* rm = Pt + 64*68;      // [64] running max
    float* rl = rm + 64;         // [64] running sum
    float* ra = rl + 64;         // [64] rescale factor

    const int tid = threadIdx.x;
    const int tx = tid & 15, ty = tid >> 4;   // tx -> k cols, ty -> q rows
    const int bh = blockIdx.y;
    const int b = bh >> 3, h = bh & 7;
    const int q0 = blockIdx.x * 64;

    const float* Qg = g_Q + (size_t)bh*NN*ND;
    const float* Kg = g_K + (size_t)bh*NN*ND;
    const float* Vg = g_V + (size_t)bh*NN*ND;
    const float* Cb = g_C + (size_t)bh*NN*S2;
    const float* Db = g_D + (size_t)bh*NN*S2;
    const float inv_scale = 0.07216878364870322f;  // 1/sqrt(192)

    const int lrow = tid >> 4, lq = tid & 15;  // per-thread load coords

    // load Q tile transposed
    #pragma unroll
    for (int it = 0; it < 4; it++) {
        int row = lrow + it*16;
        float4 v = *(const float4*)(Qg + (size_t)(q0+row)*ND + lq*4);
        Qt[(lq*4+0)*68+row] = v.x; Qt[(lq*4+1)*68+row] = v.y;
        Qt[(lq*4+2)*68+row] = v.z; Qt[(lq*4+3)*68+row] = v.w;
    }
    if (tid < 64) { rm[tid] = -1e30f; rl[tid] = 0.f; }

    float Oa[4][4];
    #pragma unroll
    for (int i = 0; i < 4; i++)
        #pragma unroll
        for (int j = 0; j < 4; j++) Oa[i][j] = 0.f;

    // prefetch first K/V tile into registers
    float4 kp[4], vp[4];
    #pragma unroll
    for (int it = 0; it < 4; it++) {
        int row = lrow + it*16;
        kp[it] = *(const float4*)(Kg + (size_t)row*ND + lq*4);
        vp[it] = *(const float4*)(Vg + (size_t)row*ND + lq*4);
    }

    for (int kt = 0; kt < 16; kt++) {
        const int k0 = kt * 64;
        __syncthreads();   // prev iter done with Kt/Vs/Pt
        #pragma unroll
        for (int it = 0; it < 4; it++) {
            int row = lrow + it*16;
            Kt[(lq*4+0)*68+row] = kp[it].x; Kt[(lq*4+1)*68+row] = kp[it].y;
            Kt[(lq*4+2)*68+row] = kp[it].z; Kt[(lq*4+3)*68+row] = kp[it].w;
            *(float4*)&Vs[row*68 + lq*4] = vp[it];
        }
        __syncthreads();

        // prefetch next tile while computing on this one
        if (kt + 1 < 16) {
            #pragma unroll
            for (int it = 0; it < 4; it++) {
                int row = lrow + it*16;
                kp[it] = *(const float4*)(Kg + (size_t)(k0+64+row)*ND + lq*4);
                vp[it] = *(const float4*)(Vg + (size_t)(k0+64+row)*ND + lq*4);
            }
        }

        // ---- S = Q K^T ----
        float s[4][4];
        #pragma unroll
        for (int i = 0; i < 4; i++)
            #pragma unroll
            for (int j = 0; j < 4; j++) s[i][j] = 0.f;
        #pragma unroll
        for (int dd = 0; dd < 64; dd++) {
            float a4[4], b4[4];
            *(float4*)a4 = *(float4*)&Qt[dd*68 + ty*4];
            *(float4*)b4 = *(float4*)&Kt[dd*68 + tx*4];
            #pragma unroll
            for (int i = 0; i < 4; i++)
                #pragma unroll
                for (int j = 0; j < 4; j++)
                    s[i][j] += a4[i]*b4[j];
        }

        // ---- add positional terms (coalesced: contiguous index innermost) ----
        // C[q,p]: p = q-k+512 is consecutive along k (j innermost)
        #pragma unroll
        for (int i = 0; i < 4; i++) {
            int qg = q0 + ty*4 + i;
            const float* Crow = Cb + (size_t)qg*S2;
            #pragma unroll
            for (int j = 0; j < 4; j++) {
                int kg = k0 + tx*4 + j;
                int p = qg - kg + SPANP;
                p = p < 0 ? 0 : (p > 1023 ? 1023 : p);
                s[i][j] += Crow[p];
            }
        }
        // D[k,p]: p = q-k+512 is consecutive along q (i innermost)
        #pragma unroll
        for (int j = 0; j < 4; j++) {
            int kg = k0 + tx*4 + j;
            const float* Drow = Db + (size_t)kg*S2;
            float col[4];
            #pragma unroll
            for (int i = 0; i < 4; i++) {
                int qg = q0 + ty*4 + i;
                int p = qg - kg + SPANP;
                p = p < 0 ? 0 : (p > 1023 ? 1023 : p);
                col[i] = (s[i][j] + Drow[p]) * inv_scale;
            }
            *(float4*)&Pt[(size_t)(tx*4+j)*68 + ty*4] = *(float4*)col;
        }
        __syncthreads();

        // ---- online softmax over k (4 threads per q-row) ----
        {
            int r = tid >> 2, l4 = tid & 3;
            float mx = -1e30f;
            for (int c = l4*16; c < l4*16 + 16; c++)
                mx = fmaxf(mx, Pt[c*68 + r]);
            mx = fmaxf(mx, __shfl_xor_sync(0xffffffffu, mx, 1));
            mx = fmaxf(mx, __shfl_xor_sync(0xffffffffu, mx, 2));
            float mold = rm[r];
            float mnew = fmaxf(mold, mx);
            float alpha = __expf(mold - mnew);
            float ssum = 0.f;
            for (int c = l4*16; c < l4*16 + 16; c++) {
                float e = __expf(Pt[c*68 + r] - mnew);
                Pt[c*68 + r] = e;
                ssum += e;
            }
            ssum += __shfl_xor_sync(0xffffffffu, ssum, 1);
            ssum += __shfl_xor_sync(0xffffffffu, ssum, 2);
            if (l4 == 0) { rm[r] = mnew; rl[r] = rl[r]*alpha + ssum; ra[r] = alpha; }
        }
        __syncthreads();

        // ---- rescale O, accumulate P @ V ----
        float al[4];
        #pragma unroll
        for (int i = 0; i < 4; i++) al[i] = ra[ty*4 + i];
        #pragma unroll
        for (int i = 0; i < 4; i++)
            #pragma unroll
            for (int j = 0; j < 4; j++) Oa[i][j] *= al[i];
        #pragma unroll
        for (int kk = 0; kk < 64; kk++) {
            float p4[4], v4[4];
            *(float4*)p4 = *(float4*)&Pt[kk*68 + ty*4];
            *(float4*)v4 = *(float4*)&Vs[kk*68 + tx*4];
            #pragma unroll
            for (int i = 0; i < 4; i++)
                #pragma unroll
                for (int j = 0; j < 4; j++)
                    Oa[i][j] += p4[i]*v4[j];
        }
    }

    // ---- finalize and write [B,N,C] ----
    float* Og = out + ((size_t)b*NN + q0)*NC + (size_t)h*ND;
    #pragma unroll
    for (int i = 0; i < 4; i++) {
        float inv = 1.f / rl[ty*4 + i];
        float4 v = make_float4(Oa[i][0]*inv, Oa[i][1]*inv, Oa[i][2]*inv, Oa[i][3]*inv);
        *(float4*)(Og + (size_t)(ty*4+i)*NC + tx*4) = v;
    }
}

// =====================================================================
extern "C" void kernel_launch(void* const* d_in, const int* in_sizes, int n_in,
                              void* d_out, int out_size)
{
    const float* q   = (const float*)d_in[0];
    const float* k   = (const float*)d_in[1];
    const float* v   = (const float*)d_in[2];
    const float* rel = (const float*)d_in[3];
    const float* Wq  = (const float*)d_in[4];
    const float* bq  = (const float*)d_in[5];
    const float* Wk  = (const float*)d_in[6];
    const float* bk  = (const float*)d_in[7];
    const float* Wv  = (const float*)d_in[8];
    const float* bv  = (const float*)d_in[9];
    float* out = (float*)d_out;

    dim3 thr(256);
    // projections
    proj_kernel<<<dim3(4, 64), thr>>>(q,   Wq, bq, 0, NB*NN, 0);
    proj_kernel<<<dim3(4, 64), thr>>>(k,   Wk, bk, 1, NB*NN, 0);
    proj_kernel<<<dim3(4, 64), thr>>>(v,   Wv, bv, 2, NB*NN, 0);
    proj_kernel<<<dim3(4, 8),  thr>>>(rel, Wk, bk, 3, S2,    1);
    proj_kernel<<<dim3(4, 8),  thr>>>(rel, Wq, bq, 4, S2,    1);
    // C = Q·posK^T, D = K·posQ^T
    cd_kernel<<<dim3(8, 8, NB*NH), thr>>>(0);
    cd_kernel<<<dim3(8, 8, NB*NH), thr>>>(1);
    // fused attention
    const int smem_bytes = (4*64*68 + 3*64) * (int)sizeof(float); // 70400
    cudaFuncSetAttribute(attn_kernel, cudaFuncAttributeMaxDynamicSharedMemorySize, smem_bytes);
    attn_kernel<<<dim3(16, NB*NH), thr, smem_bytes>>>(out);
}